// round 7
// baseline (speedup 1.0000x reference)
#include <cuda_runtime.h>
#include <cuda_fp16.h>
#include <float.h>
#include <math.h>

#define CCH 128
#define HWF 409600   // 640*640
#define WF 640
#define HF 640
#define TP_PIX 64
#define NTPB  (HWF / TP_PIX)   // 6400 transpose blocks
#define PPB   48               // points per g-block

// Precomputed M = W^T W in fp16 (symmetric), u = W^T b in fp32
__device__ __half d_Mh[CCH * CCH];
__device__ float  d_u[CCH];
// Transposed f1 in fp16: [H*W][128 slots]; slot s holds channel c(s) = (s&3)*32 + (s>>2)
__device__ __half d_f1t[(size_t)HWF * CCH];
// g[n] = M * r0[n] + u, stored slot-permuted to match d_f1t
__device__ float d_g[20000 * CCH];

// packed fp32x2 FMA (Blackwell)
#define FMA_F32X2(d, a, b, c) \
    asm("fma.rn.f32x2 %0, %1, %2, %3;" : "=l"(d) : "l"(a), "l"(b), "l"(c))

__device__ __forceinline__ unsigned long long pack_f32x2(float lo, float hi) {
    unsigned long long r;
    unsigned ulo = __float_as_uint(lo), uhi = __float_as_uint(hi);
    asm("mov.b64 %0, {%1, %2};" : "=l"(r) : "r"(ulo), "r"(uhi));
    return r;
}
__device__ __forceinline__ void unpack_f32x2(unsigned long long v, float& lo, float& hi) {
    unsigned ulo, uhi;
    asm("mov.b64 {%0, %1}, %2;" : "=r"(ulo), "=r"(uhi) : "l"(v));
    lo = __uint_as_float(ulo);
    hi = __uint_as_float(uhi);
}

// ---------------------------------------------------------------------------
// Kernel 1: M = W^T W (fp16), u = W^T b. Block o computes row o.
__global__ void precompute_Mu(const float* __restrict__ W, const float* __restrict__ b) {
    __shared__ float wcol[CCH];
    int o = blockIdx.x, t = threadIdx.x;
    wcol[t] = W[t * CCH + o];
    __syncthreads();
    float acc = 0.f;
#pragma unroll 8
    for (int k = 0; k < CCH; k++) acc += wcol[k] * W[k * CCH + t];
    d_Mh[o * CCH + t] = __float2half(acc);
    if (t == 0) {
        float uu = 0.f;
        for (int k = 0; k < CCH; k++) uu += wcol[k] * b[k];
        d_u[o] = uu;
    }
}

// ---------------------------------------------------------------------------
// Fused kernel: every 16th block (sub==15) is a g-block; the rest transpose f1.
// Dynamic smem (bytes):
//   g path:  Msh  __half[16384]  @ 0      (32768)
//            ush  float[128]     @ 32768  (512)
//            r0p  float[128*20]  @ 33280  (10240)   (pitch 20 -> 16B aligned u64 rows)
//            hi   int[16]        @ 43520  (64)
//   tp path: tile float[128*65]  @ 0      (33280)
#define R0PITCH 20
#define FUSED_SMEM 43584

__global__ void __launch_bounds__(256)
fused_tp_g(const float* __restrict__ f1,
           const float* __restrict__ mk0, const float* __restrict__ f0,
           const int* __restrict__ stride_ptr, int N)
{
    extern __shared__ char smraw[];
    const int t = threadIdx.x;
    const int sub = blockIdx.x & 15, group = blockIdx.x >> 4;

    if (sub != 15) {
        // ---------------- transpose path ----------------
        const int tidx = group * 15 + sub;
        if (tidx >= NTPB) return;
        float* tile = (float*)smraw;
        const int pb = tidx * TP_PIX;
        const int lane = t & 31, wid = t >> 5;

        // Load: coalesced float4 LDG; scalar STS into pitch-65 tile.
#pragma unroll
        for (int it = 0; it < 8; it++) {
            int idx = it * 256 + t;
            int c = idx >> 4;        // 0..127
            int g = idx & 15;        // float4 group within the 64-pixel row
            float4 v = __ldg((const float4*)(f1 + (size_t)c * HWF + pb + 4 * g));
            float* dst = &tile[c * 65 + 4 * g];
            dst[0] = v.x; dst[1] = v.y; dst[2] = v.z; dst[3] = v.w;
        }
        __syncthreads();

        // Column reads: bank = (lane + p) % 32 -> conflict-free. Pack slots 4l..4l+3.
#pragma unroll
        for (int pass = 0; pass < 8; pass++) {
            int p = pass * 8 + wid;
            float v0 = tile[(lane      ) * 65 + p];
            float v1 = tile[(lane + 32 ) * 65 + p];
            float v2 = tile[(lane + 64 ) * 65 + p];
            float v3 = tile[(lane + 96 ) * 65 + p];
            __half2 h0 = __floats2half2_rn(v0, v1);
            __half2 h1 = __floats2half2_rn(v2, v3);
            uint2 u;
            u.x = *reinterpret_cast<unsigned*>(&h0);
            u.y = *reinterpret_cast<unsigned*>(&h1);
            *reinterpret_cast<uint2*>(d_f1t + (size_t)(pb + p) * CCH + lane * 4) = u;
        }
        return;
    }

    // ---------------- g path: g[n] = M * r0[n] + u ----------------
    const int n0blk = group * PPB;
    if (n0blk >= N) return;

    __half* Msh = (__half*)smraw;
    float*  ush = (float*)(smraw + 32768);
    float*  r0p = (float*)(smraw + 33280);
    int*    hi  = (int*)(smraw + 43520);

    const int stride = stride_ptr ? __ldg(stride_ptr) : 8;
    const int fr = stride >> 1;

    {   // stage fp16 M (uint4) and u
        const uint4* Ms = (const uint4*)d_Mh;
        uint4* Md = (uint4*)Msh;
#pragma unroll
        for (int i = 0; i < 8; i++) Md[i * 256 + t] = __ldg(&Ms[i * 256 + t]);
        if (t < CCH) ush[t] = d_u[t];
    }

    const int o    = t & 127;
    const int half = t >> 7;

    for (int nb = 0; nb < PPB; nb += 16) {
        const int n0 = n0blk + nb;
        if (n0 >= N) break;
        __syncthreads();

        if (t < 16) {
            int n = n0 + t;
            int nc = n < N ? n : N - 1;
            float m0x = mk0[2 * nc], m0y = mk0[2 * nc + 1];
            int cx0 = (int)(m0x * (float)fr), cy0 = (int)(m0y * (float)fr);
            int cx0c = min(max(cx0, 2), WF - 3), cy0c = min(max(cy0, 2), HF - 3);
            hi[t] = cy0c * WF + cx0c;
        }
        __syncthreads();

        {   // gather 8 center values per thread (its half's 8 points, channel o)
            const float* fp = f0 + (size_t)o * HWF;
#pragma unroll
            for (int k = 0; k < 8; k++) {
                int q = half * 8 + k;
                r0p[o * R0PITCH + q] = __ldg(fp + hi[q]);
            }
        }
        __syncthreads();

        {   // matvec: 8 points per half-block via 4 packed f32x2 accumulators
            float uo = ush[o];
            unsigned long long a0 = pack_f32x2(uo, uo);
            unsigned long long a1 = a0, a2 = a0, a3 = a0;
#pragma unroll 8
            for (int c = 0; c < CCH; c++) {
                float m = __half2float(Msh[c * CCH + o]);
                unsigned long long m2 = pack_f32x2(m, m);
                const unsigned long long* rp =
                    (const unsigned long long*)&r0p[c * R0PITCH + half * 8];
                unsigned long long r01 = rp[0], r23 = rp[1], r45 = rp[2], r67 = rp[3];
                FMA_F32X2(a0, m2, r01, a0);
                FMA_F32X2(a1, m2, r23, a1);
                FMA_F32X2(a2, m2, r45, a2);
                FMA_F32X2(a3, m2, r67, a3);
            }
            float g[8];
            unpack_f32x2(a0, g[0], g[1]);
            unpack_f32x2(a1, g[2], g[3]);
            unpack_f32x2(a2, g[4], g[5]);
            unpack_f32x2(a3, g[6], g[7]);
            const int s = (o & 31) * 4 + (o >> 5);   // slot for channel o
#pragma unroll
            for (int k = 0; k < 8; k++) {
                int n = n0 + half * 8 + k;
                if (n < N) d_g[(size_t)n * CCH + s] = g[k];
            }
        }
    }
}

// ---------------------------------------------------------------------------
// Kernel 3: one warp per point: correlation (fp16 f1t) + softmax + outputs.
__global__ void __launch_bounds__(256)
corr_kernel(const float* __restrict__ mk0, const float* __restrict__ mk1,
            const int* __restrict__ stride_ptr, float* __restrict__ out, int N)
{
    const int wid = threadIdx.x >> 5, lane = threadIdx.x & 31;
    const int n = blockIdx.x * 8 + wid;
    if (n >= N) return;

    const int stride = stride_ptr ? __ldg(stride_ptr) : 8;
    const int fr = stride >> 1;
    const float scalef = (float)(stride / fr);
    const float halfstr = (float)(stride >> 1);

    const float m0x = __ldg(&mk0[2 * n]), m0y = __ldg(&mk0[2 * n + 1]);
    const float m1x = __ldg(&mk1[2 * n]), m1y = __ldg(&mk1[2 * n + 1]);
    const int cx0 = (int)(m0x * (float)fr), cy0 = (int)(m0y * (float)fr);
    const int cx1 = (int)(m1x * (float)fr), cy1 = (int)(m1y * (float)fr);
    const bool valid = cx0 >= 2 && cx0 + 2 < WF && cy0 >= 2 && cy0 + 2 < HF &&
                       cx1 >= 2 && cx1 + 2 < WF && cy1 >= 2 && cy1 + 2 < HF;
    const int cx1c = min(max(cx1, 2), WF - 3);
    const int cy1c = min(max(cy1, 2), HF - 3);
    const size_t pixb = (size_t)cy1c * WF + cx1c;

    // slots 4*lane..4*lane+3 (d_g written with matching permutation)
    const float4 g4 = *(const float4*)&d_g[(size_t)n * CCH + lane * 4];

    float corr = -FLT_MAX;   // lane p (p<25) ends up holding corr[p]
#pragma unroll
    for (int row = 0; row < 5; row++) {
        const size_t rb = (pixb + (size_t)(row - 2) * WF - 2) * CCH + lane * 4;
        float r[5];
#pragma unroll
        for (int col = 0; col < 5; col++) {
            uint2 u = __ldg((const uint2*)(d_f1t + rb + (size_t)col * CCH));
            __half2 h0 = *reinterpret_cast<__half2*>(&u.x);
            __half2 h1 = *reinterpret_cast<__half2*>(&u.y);
            float2 f01 = __half22float2(h0);
            float2 f23 = __half22float2(h1);
            r[col] = g4.x * f01.x + g4.y * f01.y + g4.z * f23.x + g4.w * f23.y;
        }
#pragma unroll
        for (int d = 16; d; d >>= 1) {
            r[0] += __shfl_xor_sync(0xffffffffu, r[0], d);
            r[1] += __shfl_xor_sync(0xffffffffu, r[1], d);
            r[2] += __shfl_xor_sync(0xffffffffu, r[2], d);
            r[3] += __shfl_xor_sync(0xffffffffu, r[3], d);
            r[4] += __shfl_xor_sync(0xffffffffu, r[4], d);
        }
        const int p0 = row * 5;
#pragma unroll
        for (int col = 0; col < 5; col++)
            if (lane == p0 + col) corr = r[col];
    }

    // softmax over lanes 0..24 + expectation (per-point constant cancels)
    const bool inpatch = lane < 25;
    const int dx = lane % 5 - 2;
    const int dy = lane / 5 - 2;
    float cm = corr;
#pragma unroll
    for (int d = 16; d; d >>= 1)
        cm = fmaxf(cm, __shfl_xor_sync(0xffffffffu, cm, d));
    float e  = inpatch ? __expf(corr - cm) : 0.f;
    float ex = e * (float)dx;
    float ey = e * (float)dy;
    float s  = e;
#pragma unroll
    for (int d = 16; d; d >>= 1) {
        s  += __shfl_xor_sync(0xffffffffu, s,  d);
        ex += __shfl_xor_sync(0xffffffffu, ex, d);
        ey += __shfl_xor_sync(0xffffffffu, ey, d);
    }
    if (lane == 0) {
        out[2 * n]     = m0x * (float)stride + halfstr;
        out[2 * n + 1] = m0y * (float)stride + halfstr;
        const float inv = scalef / s;
        const float ox = valid ? ex * inv : 0.f;
        const float oy = valid ? ey * inv : 0.f;
        out[2 * N + 2 * n]     = m1x * (float)stride + halfstr + ox;
        out[2 * N + 2 * n + 1] = m1y * (float)stride + halfstr + oy;
    }
}

// ---------------------------------------------------------------------------
extern "C" void kernel_launch(void* const* d_in, const int* in_sizes, int n_in,
                              void* d_out, int out_size) {
    const float* mk0 = (const float*)d_in[0];
    const float* mk1 = (const float*)d_in[1];
    const float* f0  = (const float*)d_in[2];
    const float* f1  = (const float*)d_in[3];
    const float* pw  = (const float*)d_in[4];
    const float* pb  = (const float*)d_in[5];
    const int* stridep = (n_in >= 7) ? (const int*)d_in[6] : nullptr;
    float* out = (float*)d_out;

    int N = in_sizes[0] / 2;

    precompute_Mu<<<128, 128>>>(pw, pb);

    // groups of 16 blocks: 15 transpose + 1 g-block
    int ngb = (N + PPB - 1) / PPB;                 // g-blocks needed
    int tpgroups = (NTPB + 14) / 15;               // 427
    int groups = tpgroups > ngb ? tpgroups : ngb;
    cudaFuncSetAttribute(fused_tp_g,
                         cudaFuncAttributeMaxDynamicSharedMemorySize, FUSED_SMEM);
    fused_tp_g<<<groups * 16, 256, FUSED_SMEM>>>(f1, mk0, f0, stridep, N);

    corr_kernel<<<(N + 7) / 8, 256>>>(mk0, mk1, stridep, out, N);
}

// round 8
// speedup vs baseline: 1.0184x; 1.0184x over previous
#include <cuda_runtime.h>
#include <cuda_fp16.h>
#include <float.h>
#include <math.h>

#define CCH 128
#define HWF 409600   // 640*640
#define WF 640
#define HF 640
#define TPPIX 128
#define NTPB (HWF / TPPIX)   // 3200 transpose blocks
#define PPB 32               // points per g-block

// Precomputed M = W^T W in fp16 (symmetric), u = W^T b in fp32
__device__ __half d_Mh[CCH * CCH];
__device__ float  d_u[CCH];
// Transposed f1 in fp16: [H*W][128 slots]; slot s holds channel c(s) = (s&3)*32 + (s>>2)
__device__ __half d_f1t[(size_t)HWF * CCH];
// g[n] = M * r0[n] + u, stored slot-permuted to match d_f1t
__device__ float d_g[20000 * CCH];

// packed fp32x2 FMA (Blackwell)
#define FMA_F32X2(d, a, b, c) \
    asm("fma.rn.f32x2 %0, %1, %2, %3;" : "=l"(d) : "l"(a), "l"(b), "l"(c))

__device__ __forceinline__ unsigned long long pack_f32x2(float lo, float hi) {
    unsigned long long r;
    unsigned ulo = __float_as_uint(lo), uhi = __float_as_uint(hi);
    asm("mov.b64 %0, {%1, %2};" : "=l"(r) : "r"(ulo), "r"(uhi));
    return r;
}
__device__ __forceinline__ void unpack_f32x2(unsigned long long v, float& lo, float& hi) {
    unsigned ulo, uhi;
    asm("mov.b64 {%0, %1}, %2;" : "=r"(ulo), "=r"(uhi) : "l"(v));
    lo = __uint_as_float(ulo);
    hi = __uint_as_float(uhi);
}

// ---------------------------------------------------------------------------
// Kernel A: blocks [0, NTPB): register transpose f1 -> d_f1t (fp16, slot-permuted)
//           blocks [NTPB, NTPB+128): precompute M (fp16) and u (runs before g_kernel)
__global__ void __launch_bounds__(256)
transpose_f1(const float* __restrict__ f1,
             const float* __restrict__ W, const float* __restrict__ b)
{
    __shared__ float wcol[CCH];
    const int blk = blockIdx.x;
    const int t = threadIdx.x;

    if (blk >= NTPB) {
        // ---- precompute role: row o of M = W^T W, u[o] ----
        const int o = blk - NTPB;
        if (t < CCH) {
            wcol[t] = W[t * CCH + o];
        }
        __syncthreads();
        if (t < CCH) {
            float acc = 0.f;
#pragma unroll 8
            for (int k = 0; k < CCH; k++) acc += wcol[k] * W[k * CCH + t];
            d_Mh[o * CCH + t] = __float2half(acc);
            if (t == 0) {
                float uu = 0.f;
                for (int k = 0; k < CCH; k++) uu += wcol[k] * b[k];
                d_u[o] = uu;
            }
        }
        return;
    }

    // ---- transpose role: 128 pixels per block, no smem ----
    // thread (w = t>>5, l = t&31): channels cb = 4w..4w+3 (+32k), pixels pb+4l..+3
    const int w = t >> 5, l = t & 31;
    const size_t pb = (size_t)blk * TPPIX;

    float4 v[4][4];   // v[j][k] = pixels (pb+4l..+3) of channel 4w+j+32k
#pragma unroll
    for (int j = 0; j < 4; j++)
#pragma unroll
        for (int k = 0; k < 4; k++)
            v[j][k] = __ldg((const float4*)(f1 + (size_t)(4 * w + j + 32 * k) * HWF
                                            + pb + 4 * l));

#pragma unroll
    for (int j2 = 0; j2 < 4; j2++) {
        // pixel p = pb + 4l + j2; slots 16w+4j+k hold channel 32k + (4w+j)
        unsigned q[8];
#pragma unroll
        for (int j = 0; j < 4; j++) {
            const float* v0 = (const float*)&v[j][0];
            const float* v1 = (const float*)&v[j][1];
            const float* v2 = (const float*)&v[j][2];
            const float* v3 = (const float*)&v[j][3];
            __half2 h0 = __floats2half2_rn(v0[j2], v1[j2]);
            __half2 h1 = __floats2half2_rn(v2[j2], v3[j2]);
            q[2 * j]     = *reinterpret_cast<unsigned*>(&h0);
            q[2 * j + 1] = *reinterpret_cast<unsigned*>(&h1);
        }
        __half* dst = d_f1t + (pb + 4 * l + j2) * CCH + 16 * w;
        *reinterpret_cast<uint4*>(dst)     = make_uint4(q[0], q[1], q[2], q[3]);
        *reinterpret_cast<uint4*>(dst + 8) = make_uint4(q[4], q[5], q[6], q[7]);
    }
}

// ---------------------------------------------------------------------------
// Kernel B: g[n] = M * r0[n] + u  (fp16 M in smem, FFMA2 matvec, 16-pt batches)
// smem bytes: Msh half[16384]@0 (32768), ush float[128]@32768 (512),
//             r0p float[128*20]@33280 (10240), hi int[16]@43520 (64)
#define R0PITCH 20
#define G_SMEM 43584
__global__ void __launch_bounds__(256)
g_kernel(const float* __restrict__ mk0, const float* __restrict__ f0,
         const int* __restrict__ stride_ptr, int N)
{
    extern __shared__ char smraw[];
    __half* Msh = (__half*)smraw;
    float*  ush = (float*)(smraw + 32768);
    float*  r0p = (float*)(smraw + 33280);
    int*    hi  = (int*)(smraw + 43520);

    const int t = threadIdx.x;
    const int stride = stride_ptr ? __ldg(stride_ptr) : 8;
    const int fr = stride >> 1;

    {   // stage fp16 M (uint4) and u
        const uint4* Ms = (const uint4*)d_Mh;
        uint4* Md = (uint4*)Msh;
#pragma unroll
        for (int i = 0; i < 8; i++) Md[i * 256 + t] = __ldg(&Ms[i * 256 + t]);
        if (t < CCH) ush[t] = d_u[t];
    }

    const int o    = t & 127;
    const int half = t >> 7;
    const int n0blk = blockIdx.x * PPB;

    for (int nb = 0; nb < PPB; nb += 16) {
        const int n0 = n0blk + nb;
        if (n0 >= N) break;
        __syncthreads();

        if (t < 16) {
            int n = n0 + t;
            int nc = n < N ? n : N - 1;
            float m0x = mk0[2 * nc], m0y = mk0[2 * nc + 1];
            int cx0 = (int)(m0x * (float)fr), cy0 = (int)(m0y * (float)fr);
            int cx0c = min(max(cx0, 2), WF - 3), cy0c = min(max(cy0, 2), HF - 3);
            hi[t] = cy0c * WF + cx0c;
        }
        __syncthreads();

        {   // gather 8 center values per thread (its half's 8 points, channel o)
            const float* fp = f0 + (size_t)o * HWF;
#pragma unroll
            for (int k = 0; k < 8; k++) {
                int q = half * 8 + k;
                r0p[o * R0PITCH + q] = __ldg(fp + hi[q]);
            }
        }
        __syncthreads();

        {   // matvec: 8 points per half-block via 4 packed f32x2 accumulators
            float uo = ush[o];
            unsigned long long a0 = pack_f32x2(uo, uo);
            unsigned long long a1 = a0, a2 = a0, a3 = a0;
#pragma unroll 8
            for (int c = 0; c < CCH; c++) {
                float m = __half2float(Msh[c * CCH + o]);
                unsigned long long m2 = pack_f32x2(m, m);
                const unsigned long long* rp =
                    (const unsigned long long*)&r0p[c * R0PITCH + half * 8];
                unsigned long long r01 = rp[0], r23 = rp[1], r45 = rp[2], r67 = rp[3];
                FMA_F32X2(a0, m2, r01, a0);
                FMA_F32X2(a1, m2, r23, a1);
                FMA_F32X2(a2, m2, r45, a2);
                FMA_F32X2(a3, m2, r67, a3);
            }
            float g[8];
            unpack_f32x2(a0, g[0], g[1]);
            unpack_f32x2(a1, g[2], g[3]);
            unpack_f32x2(a2, g[4], g[5]);
            unpack_f32x2(a3, g[6], g[7]);
            const int s = (o & 31) * 4 + (o >> 5);   // slot for channel o
#pragma unroll
            for (int k = 0; k < 8; k++) {
                int n = n0 + half * 8 + k;
                if (n < N) d_g[(size_t)n * CCH + s] = g[k];
            }
        }
    }
}

// ---------------------------------------------------------------------------
// Kernel C: one warp per point: correlation (fp16 f1t) + softmax + outputs.
__global__ void __launch_bounds__(256)
corr_kernel(const float* __restrict__ mk0, const float* __restrict__ mk1,
            const int* __restrict__ stride_ptr, float* __restrict__ out, int N)
{
    const int wid = threadIdx.x >> 5, lane = threadIdx.x & 31;
    const int n = blockIdx.x * 8 + wid;
    if (n >= N) return;

    const int stride = stride_ptr ? __ldg(stride_ptr) : 8;
    const int fr = stride >> 1;
    const float scalef = (float)(stride / fr);
    const float halfstr = (float)(stride >> 1);

    const float m0x = __ldg(&mk0[2 * n]), m0y = __ldg(&mk0[2 * n + 1]);
    const float m1x = __ldg(&mk1[2 * n]), m1y = __ldg(&mk1[2 * n + 1]);
    const int cx0 = (int)(m0x * (float)fr), cy0 = (int)(m0y * (float)fr);
    const int cx1 = (int)(m1x * (float)fr), cy1 = (int)(m1y * (float)fr);
    const bool valid = cx0 >= 2 && cx0 + 2 < WF && cy0 >= 2 && cy0 + 2 < HF &&
                       cx1 >= 2 && cx1 + 2 < WF && cy1 >= 2 && cy1 + 2 < HF;
    const int cx1c = min(max(cx1, 2), WF - 3);
    const int cy1c = min(max(cy1, 2), HF - 3);
    const size_t pixb = (size_t)cy1c * WF + cx1c;

    // slots 4*lane..4*lane+3 (d_g written with matching permutation)
    const float4 g4 = *(const float4*)&d_g[(size_t)n * CCH + lane * 4];

    float corr = -FLT_MAX;   // lane p (p<25) ends up holding corr[p]
#pragma unroll
    for (int row = 0; row < 5; row++) {
        const size_t rb = (pixb + (size_t)(row - 2) * WF - 2) * CCH + lane * 4;
        float r[5];
#pragma unroll
        for (int col = 0; col < 5; col++) {
            uint2 u = __ldg((const uint2*)(d_f1t + rb + (size_t)col * CCH));
            __half2 h0 = *reinterpret_cast<__half2*>(&u.x);
            __half2 h1 = *reinterpret_cast<__half2*>(&u.y);
            float2 f01 = __half22float2(h0);
            float2 f23 = __half22float2(h1);
            r[col] = g4.x * f01.x + g4.y * f01.y + g4.z * f23.x + g4.w * f23.y;
        }
#pragma unroll
        for (int d = 16; d; d >>= 1) {
            r[0] += __shfl_xor_sync(0xffffffffu, r[0], d);
            r[1] += __shfl_xor_sync(0xffffffffu, r[1], d);
            r[2] += __shfl_xor_sync(0xffffffffu, r[2], d);
            r[3] += __shfl_xor_sync(0xffffffffu, r[3], d);
            r[4] += __shfl_xor_sync(0xffffffffu, r[4], d);
        }
        const int p0 = row * 5;
#pragma unroll
        for (int col = 0; col < 5; col++)
            if (lane == p0 + col) corr = r[col];
    }

    // softmax over lanes 0..24 + expectation (per-point constant cancels)
    const bool inpatch = lane < 25;
    const int dx = lane % 5 - 2;
    const int dy = lane / 5 - 2;
    float cm = corr;
#pragma unroll
    for (int d = 16; d; d >>= 1)
        cm = fmaxf(cm, __shfl_xor_sync(0xffffffffu, cm, d));
    float e  = inpatch ? __expf(corr - cm) : 0.f;
    float ex = e * (float)dx;
    float ey = e * (float)dy;
    float s  = e;
#pragma unroll
    for (int d = 16; d; d >>= 1) {
        s  += __shfl_xor_sync(0xffffffffu, s,  d);
        ex += __shfl_xor_sync(0xffffffffu, ex, d);
        ey += __shfl_xor_sync(0xffffffffu, ey, d);
    }
    if (lane == 0) {
        out[2 * n]     = m0x * (float)stride + halfstr;
        out[2 * n + 1] = m0y * (float)stride + halfstr;
        const float inv = scalef / s;
        const float ox = valid ? ex * inv : 0.f;
        const float oy = valid ? ey * inv : 0.f;
        out[2 * N + 2 * n]     = m1x * (float)stride + halfstr + ox;
        out[2 * N + 2 * n + 1] = m1y * (float)stride + halfstr + oy;
    }
}

// ---------------------------------------------------------------------------
extern "C" void kernel_launch(void* const* d_in, const int* in_sizes, int n_in,
                              void* d_out, int out_size) {
    const float* mk0 = (const float*)d_in[0];
    const float* mk1 = (const float*)d_in[1];
    const float* f0  = (const float*)d_in[2];
    const float* f1  = (const float*)d_in[3];
    const float* pw  = (const float*)d_in[4];
    const float* pb  = (const float*)d_in[5];
    const int* stridep = (n_in >= 7) ? (const int*)d_in[6] : nullptr;
    float* out = (float*)d_out;

    int N = in_sizes[0] / 2;

    // transpose f1 + (last 128 blocks) precompute M,u
    transpose_f1<<<NTPB + 128, 256>>>(f1, pw, pb);

    cudaFuncSetAttribute(g_kernel,
                         cudaFuncAttributeMaxDynamicSharedMemorySize, G_SMEM);
    g_kernel<<<(N + PPB - 1) / PPB, 256, G_SMEM>>>(mk0, f0, stridep, N);

    corr_kernel<<<(N + 7) / 8, 256>>>(mk0, mk1, stridep, out, N);
}